// round 2
// baseline (speedup 1.0000x reference)
#include <cuda_runtime.h>
#include <cstdint>

#define RES    300
#define NCOMP  48
#define NFEAT  27
#define NPAD   28          // pad 27 -> 28 so each W row is 7 x 16B
#define KTOT   (3*NCOMP)   // 144

// Scratch: channel-last transposed copies (allowed: __device__ globals, no alloc).
__device__ __align__(16) float g_planesT[3u * RES * RES * NCOMP]; // [i][y][x][c]
__device__ __align__(16) float g_linesT [3u * RES * NCOMP];       // [i][r][c]

// ---------------------------------------------------------------------------
// Transpose planes (3,48,300,300) -> (3,300,300,48) via shared tile.
// ---------------------------------------------------------------------------
__global__ void transpose_planes_kernel(const float* __restrict__ planes) {
    __shared__ float tile[NCOMP][33];
    const int i  = blockIdx.z;
    const int y  = blockIdx.y;
    const int xt = blockIdx.x * 32;
    const int t  = threadIdx.x;
    const int tx = t & 31;
    const int tc = t >> 5;             // 0..7
    const int x  = xt + tx;

    #pragma unroll
    for (int r = 0; r < 6; r++) {
        const int c = tc + 8 * r;      // covers 0..47
        if (x < RES)
            tile[c][tx] = planes[(((size_t)i * NCOMP + c) * RES + y) * RES + x];
    }
    __syncthreads();

    const int nx = min(32, RES - xt);
    float* outb = g_planesT + (((size_t)i * RES + y) * RES + xt) * NCOMP;
    for (int e = t; e < nx * NCOMP; e += 256) {
        const int xl = e / NCOMP;
        const int c  = e - xl * NCOMP;
        outb[e] = tile[c][xl];
    }
}

// Transpose lines (3,48,300,1) -> (3,300,48). Output-coalesced.
__global__ void transpose_lines_kernel(const float* __restrict__ lines) {
    const int e = blockIdx.x * 256 + threadIdx.x;
    if (e >= 3 * RES * NCOMP) return;
    const int c  = e % NCOMP;
    const int ir = e / NCOMP;
    const int r  = ir % RES;
    const int i  = ir / RES;
    g_linesT[e] = lines[((size_t)i * NCOMP + c) * RES + r];
}

// ---------------------------------------------------------------------------
// Packed f32x2 helpers (Blackwell): 2 fp32 FMAs per instruction.
// ---------------------------------------------------------------------------
__device__ __forceinline__ void fma2(unsigned long long& d,
                                     unsigned long long a,
                                     unsigned long long b) {
    asm("fma.rn.f32x2 %0, %1, %2, %0;" : "+l"(d) : "l"(a), "l"(b));
}
__device__ __forceinline__ unsigned long long pack2(float f) {
    unsigned long long r;
    asm("mov.b64 %0, {%1, %1};" : "=l"(r) : "f"(f));
    return r;
}
__device__ __forceinline__ void unpack2(unsigned long long v, float& lo, float& hi) {
    asm("mov.b64 {%0, %1}, %2;" : "=f"(lo), "=f"(hi) : "l"(v));
}

// Per-channel: bilinear*line feature, then 14 packed FMAs into acc (28 lanes of j).
__device__ __forceinline__ void do_channel(float v00, float v01, float v10, float v11,
                                           float L0, float L1,
                                           float w00, float w01, float w10, float w11,
                                           float lw0, float lw1,
                                           const float* __restrict__ wrow,
                                           unsigned long long* acc) {
    const float pf = w00 * v00 + w01 * v01 + w10 * v10 + w11 * v11;
    const float lf = lw0 * L0 + lw1 * L1;
    const unsigned long long ff = pack2(pf * lf);
    const ulonglong2* wr = reinterpret_cast<const ulonglong2*>(wrow);
    #pragma unroll
    for (int q = 0; q < 7; q++) {
        ulonglong2 w = wr[q];            // LDS.128
        fma2(acc[2 * q],     w.x, ff);
        fma2(acc[2 * q + 1], w.y, ff);
    }
}

// ---------------------------------------------------------------------------
// Main: FOUR threads per point. sub = t&3 owns channels {q*16+sub*4 .. +3 : q<3}.
// Per tap, instruction q has 4 lanes covering 64B contiguous -> coalesced gather.
// ---------------------------------------------------------------------------
__global__ __launch_bounds__(256)
void tvm_main_kernel(const float* __restrict__ xyz,
                     const float* __restrict__ basisW,
                     float* __restrict__ out,
                     int npts) {
    __shared__ __align__(16) float sW[KTOT * NPAD]; // sW[k*28 + j] = W[j][k]

    for (int e = threadIdx.x; e < KTOT * NPAD; e += 256) {
        const int k = e / NPAD;
        const int j = e - k * NPAD;
        sW[e] = (j < NFEAT) ? basisW[j * KTOT + k] : 0.0f;
    }
    __syncthreads();

    const int t   = blockIdx.x * 256 + threadIdx.x;
    const int n   = t >> 2;            // point index
    const int sub = t & 3;             // channel-slice index 0..3
    if (n >= npts) return;

    const float p0 = xyz[3 * n + 0];
    const float p1 = xyz[3 * n + 1];
    const float p2 = xyz[3 * n + 2];

    unsigned long long acc[14];
    #pragma unroll
    for (int q = 0; q < 14; q++) acc[q] = 0ull;

    // PLANE_AX = ((2,1),(2,0),(1,0)): gx = p[a], gy = p[b]; line at p[i].
    const float gxs[3] = {p2, p2, p1};
    const float gys[3] = {p1, p0, p0};
    const float gzs[3] = {p0, p1, p2};

    #pragma unroll
    for (int i = 0; i < 3; i++) {
        const float sc = 0.5f * (float)(RES - 1);
        const float x = (gxs[i] + 1.0f) * sc;
        const float y = (gys[i] + 1.0f) * sc;
        const float z = (gzs[i] + 1.0f) * sc;
        const float xf = floorf(x), yf = floorf(y), zf = floorf(z);
        const float wx = x - xf, wy = y - yf, wz = z - zf;
        const int x0 = min(max((int)xf, 0), RES - 1); const int x1 = min(x0 + 1, RES - 1);
        const int y0 = min(max((int)yf, 0), RES - 1); const int y1 = min(y0 + 1, RES - 1);
        const int z0 = min(max((int)zf, 0), RES - 1); const int z1 = min(z0 + 1, RES - 1);

        const float w00 = (1.0f - wx) * (1.0f - wy);
        const float w01 = wx * (1.0f - wy);
        const float w10 = (1.0f - wx) * wy;
        const float w11 = wx * wy;
        const float lw0 = 1.0f - wz;
        const float lw1 = wz;

        const float* P = g_planesT + (size_t)i * RES * RES * NCOMP;
        const float4* r00 = (const float4*)(P + ((size_t)y0 * RES + x0) * NCOMP);
        const float4* r01 = (const float4*)(P + ((size_t)y0 * RES + x1) * NCOMP);
        const float4* r10 = (const float4*)(P + ((size_t)y1 * RES + x0) * NCOMP);
        const float4* r11 = (const float4*)(P + ((size_t)y1 * RES + x1) * NCOMP);
        const float4* l0  = (const float4*)(g_linesT + ((size_t)i * RES + z0) * NCOMP);
        const float4* l1  = (const float4*)(g_linesT + ((size_t)i * RES + z1) * NCOMP);
        const float* wb = sW + i * NCOMP * NPAD;

        #pragma unroll
        for (int q = 0; q < 3; q++) {
            const int idx = q * 4 + sub;          // float4 index within the 48ch tap
            const float4 v00 = r00[idx];          // lanes of one point cover 64B contig
            const float4 v01 = r01[idx];
            const float4 v10 = r10[idx];
            const float4 v11 = r11[idx];
            const float4 L0  = l0[idx];
            const float4 L1  = l1[idx];
            const float* wrow = wb + (idx * 4) * NPAD;
            do_channel(v00.x, v01.x, v10.x, v11.x, L0.x, L1.x,
                       w00, w01, w10, w11, lw0, lw1, wrow + 0 * NPAD, acc);
            do_channel(v00.y, v01.y, v10.y, v11.y, L0.y, L1.y,
                       w00, w01, w10, w11, lw0, lw1, wrow + 1 * NPAD, acc);
            do_channel(v00.z, v01.z, v10.z, v11.z, L0.z, L1.z,
                       w00, w01, w10, w11, lw0, lw1, wrow + 2 * NPAD, acc);
            do_channel(v00.w, v01.w, v10.w, v11.w, L0.w, L1.w,
                       w00, w01, w10, w11, lw0, lw1, wrow + 3 * NPAD, acc);
        }
    }

    // Unpack partial sums and butterfly-reduce across the 4-lane point group.
    float f[NFEAT];
    #pragma unroll
    for (int j = 0; j < NFEAT; j++) {
        float lo, hi;
        unpack2(acc[j >> 1], lo, hi);
        f[j] = (j & 1) ? hi : lo;
    }
    #pragma unroll
    for (int r = 1; r <= 2; r <<= 1) {
        #pragma unroll
        for (int j = 0; j < NFEAT; j++)
            f[j] += __shfl_xor_sync(0xffffffffu, f[j], r);
    }

    // Each sub stores a 7-float slice (sub 3 stores 6).
    float* o = out + (size_t)n * NFEAT;
    const int jb = sub * 7;
    const int je = min(jb + 7, NFEAT);
    for (int j = jb; j < je; j++) o[j] = f[j];
}

// ---------------------------------------------------------------------------
extern "C" void kernel_launch(void* const* d_in, const int* in_sizes, int n_in,
                              void* d_out, int out_size) {
    const float* xyz    = (const float*)d_in[0];
    const float* planes = (const float*)d_in[1];
    const float* lines  = (const float*)d_in[2];
    const float* basisW = (const float*)d_in[3];
    float* out = (float*)d_out;
    const int npts = in_sizes[0] / 3;

    dim3 tg((RES + 31) / 32, RES, 3);
    transpose_planes_kernel<<<tg, 256>>>(planes);
    transpose_lines_kernel<<<(3 * RES * NCOMP + 255) / 256, 256>>>(lines);
    const long long nthreads = (long long)npts * 4;
    tvm_main_kernel<<<(int)((nthreads + 255) / 256), 256>>>(xyz, basisW, out, npts);
}

// round 3
// speedup vs baseline: 2.5684x; 2.5684x over previous
#include <cuda_runtime.h>
#include <cuda_fp16.h>
#include <cstdint>

#define RES    300
#define NCOMP  48
#define NFEAT  27
#define NPAD   28          // pad 27 -> 28 so each W row is 7 x 16B
#define KTOT   (3*NCOMP)   // 144
#define OPAD   30          // output staging row pad (even -> 8B-aligned STS.64)
#define PTS_PER_BLK 256    // 128 threads x 2 points

// Scratch: channel-last transposed fp16 copies (no allocs; __device__ globals).
__device__ __align__(16) __half g_planesH[3u * RES * RES * NCOMP]; // [i][y][x][c]
__device__ __align__(16) __half g_linesH [3u * RES * NCOMP];       // [i][r][c]

// ---------------------------------------------------------------------------
// Transpose planes (3,48,300,300) -> fp16 (3,300,300,48) via shared tile.
// ---------------------------------------------------------------------------
__global__ void transpose_planes_kernel(const float* __restrict__ planes) {
    __shared__ float tile[NCOMP][33];
    const int i  = blockIdx.z;
    const int y  = blockIdx.y;
    const int xt = blockIdx.x * 32;
    const int t  = threadIdx.x;
    const int tx = t & 31;
    const int tc = t >> 5;             // 0..7
    const int x  = xt + tx;

    #pragma unroll
    for (int r = 0; r < 6; r++) {
        const int c = tc + 8 * r;      // covers 0..47
        if (x < RES)
            tile[c][tx] = planes[(((size_t)i * NCOMP + c) * RES + y) * RES + x];
    }
    __syncthreads();

    const int nx = min(32, RES - xt);
    __half* outb = g_planesH + (((size_t)i * RES + y) * RES + xt) * NCOMP;
    for (int e = t; e < nx * NCOMP; e += 256) {
        const int xl = e / NCOMP;
        const int c  = e - xl * NCOMP;
        outb[e] = __float2half(tile[c][xl]);
    }
}

// Transpose lines (3,48,300,1) -> fp16 (3,300,48).
__global__ void transpose_lines_kernel(const float* __restrict__ lines) {
    const int e = blockIdx.x * 256 + threadIdx.x;
    if (e >= 3 * RES * NCOMP) return;
    const int c  = e % NCOMP;
    const int ir = e / NCOMP;
    const int r  = ir % RES;
    const int i  = ir / RES;
    g_linesH[e] = __float2half(lines[((size_t)i * NCOMP + c) * RES + r]);
}

// ---------------------------------------------------------------------------
// Packed f32x2 helpers.
// ---------------------------------------------------------------------------
__device__ __forceinline__ void fma2(unsigned long long& d,
                                     unsigned long long a,
                                     unsigned long long b) {
    asm("fma.rn.f32x2 %0, %1, %2, %0;" : "+l"(d) : "l"(a), "l"(b));
}
__device__ __forceinline__ unsigned long long pack2(float f) {
    unsigned long long r;
    asm("mov.b64 %0, {%1, %1};" : "=l"(r) : "f"(f));
    return r;
}
__device__ __forceinline__ float2 h2f(uint32_t u) {
    return __half22float2(*reinterpret_cast<const __half2*>(&u));
}

// One channel-PAIR for TWO points: W loads (14 LDS.128) shared by both points.
__device__ __forceinline__ void chan_pair2(
    uint32_t a00, uint32_t a01, uint32_t a10, uint32_t a11, uint32_t aL0, uint32_t aL1,
    uint32_t b00, uint32_t b01, uint32_t b10, uint32_t b11, uint32_t bL0, uint32_t bL1,
    float Aw00, float Aw01, float Aw10, float Aw11, float Alw0, float Alw1,
    float Bw00, float Bw01, float Bw10, float Bw11, float Blw0, float Blw1,
    const float* __restrict__ wrow0,
    unsigned long long* accA, unsigned long long* accB)
{
    const float2 vA00 = h2f(a00), vA01 = h2f(a01), vA10 = h2f(a10), vA11 = h2f(a11);
    const float2 vAL0 = h2f(aL0), vAL1 = h2f(aL1);
    const float2 vB00 = h2f(b00), vB01 = h2f(b01), vB10 = h2f(b10), vB11 = h2f(b11);
    const float2 vBL0 = h2f(bL0), vBL1 = h2f(bL1);

    const float pfA0 = Aw00*vA00.x + Aw01*vA01.x + Aw10*vA10.x + Aw11*vA11.x;
    const float pfA1 = Aw00*vA00.y + Aw01*vA01.y + Aw10*vA10.y + Aw11*vA11.y;
    const float lfA0 = Alw0*vAL0.x + Alw1*vAL1.x;
    const float lfA1 = Alw0*vAL0.y + Alw1*vAL1.y;
    const float pfB0 = Bw00*vB00.x + Bw01*vB01.x + Bw10*vB10.x + Bw11*vB11.x;
    const float pfB1 = Bw00*vB00.y + Bw01*vB01.y + Bw10*vB10.y + Bw11*vB11.y;
    const float lfB0 = Blw0*vBL0.x + Blw1*vBL1.x;
    const float lfB1 = Blw0*vBL0.y + Blw1*vBL1.y;

    const unsigned long long ffA0 = pack2(pfA0 * lfA0);
    const unsigned long long ffA1 = pack2(pfA1 * lfA1);
    const unsigned long long ffB0 = pack2(pfB0 * lfB0);
    const unsigned long long ffB1 = pack2(pfB1 * lfB1);

    const ulonglong2* w0 = reinterpret_cast<const ulonglong2*>(wrow0);
    const ulonglong2* w1 = reinterpret_cast<const ulonglong2*>(wrow0 + NPAD);
    #pragma unroll
    for (int q = 0; q < 7; q++) {
        ulonglong2 W0 = w0[q];                // one LDS.128 serves 4 fma2
        fma2(accA[2*q],   W0.x, ffA0);
        fma2(accA[2*q+1], W0.y, ffA0);
        fma2(accB[2*q],   W0.x, ffB0);
        fma2(accB[2*q+1], W0.y, ffB0);
        ulonglong2 W1 = w1[q];
        fma2(accA[2*q],   W1.x, ffA1);
        fma2(accA[2*q+1], W1.y, ffA1);
        fma2(accB[2*q],   W1.x, ffB1);
        fma2(accB[2*q+1], W1.y, ffB1);
    }
}

// ---------------------------------------------------------------------------
// Main: 128 threads/block, 2 points per thread (A = base+tid, B = A+128).
// ---------------------------------------------------------------------------
__global__ __launch_bounds__(128, 3)
void tvm_main_kernel(const float* __restrict__ xyz,
                     const float* __restrict__ basisW,
                     float* __restrict__ out,
                     int npts) {
    __shared__ __align__(16) float sW[KTOT * NPAD];       // 16128 B
    __shared__ __align__(16) float sOut[PTS_PER_BLK * OPAD]; // 30720 B

    const int tid = threadIdx.x;
    for (int e = tid; e < KTOT * NPAD; e += 128) {
        const int k = e / NPAD;
        const int j = e - k * NPAD;
        sW[e] = (j < NFEAT) ? basisW[j * KTOT + k] : 0.0f;
    }
    __syncthreads();

    const int base = blockIdx.x * PTS_PER_BLK;
    const int nA = min(base + tid,        npts - 1);
    const int nB = min(base + tid + 128,  npts - 1);

    const float a0 = xyz[3*nA+0], a1 = xyz[3*nA+1], a2 = xyz[3*nA+2];
    const float b0 = xyz[3*nB+0], b1 = xyz[3*nB+1], b2 = xyz[3*nB+2];

    unsigned long long accA[14], accB[14];
    #pragma unroll
    for (int q = 0; q < 14; q++) { accA[q] = 0ull; accB[q] = 0ull; }

    // PLANE_AX = ((2,1),(2,0),(1,0)): gx = p[a], gy = p[b]; line coord p[i].
    #pragma unroll
    for (int i = 0; i < 3; i++) {
        float gxA, gyA, gzA, gxB, gyB, gzB;
        if (i == 0)      { gxA = a2; gyA = a1; gzA = a0;  gxB = b2; gyB = b1; gzB = b0; }
        else if (i == 1) { gxA = a2; gyA = a0; gzA = a1;  gxB = b2; gyB = b0; gzB = b1; }
        else             { gxA = a1; gyA = a0; gzA = a2;  gxB = b1; gyB = b0; gzB = b2; }

        const float sc = 0.5f * (float)(RES - 1);
        // --- point A coords ---
        const float xA = (gxA + 1.0f) * sc, yA = (gyA + 1.0f) * sc, zA = (gzA + 1.0f) * sc;
        const float xAf = floorf(xA), yAf = floorf(yA), zAf = floorf(zA);
        const float wxA = xA - xAf, wyA = yA - yAf, wzA = zA - zAf;
        const int xA0 = min(max((int)xAf, 0), RES-1); const int xA1 = min(xA0+1, RES-1);
        const int yA0 = min(max((int)yAf, 0), RES-1); const int yA1 = min(yA0+1, RES-1);
        const int zA0 = min(max((int)zAf, 0), RES-1); const int zA1 = min(zA0+1, RES-1);
        const float Aw00 = (1.0f-wxA)*(1.0f-wyA), Aw01 = wxA*(1.0f-wyA);
        const float Aw10 = (1.0f-wxA)*wyA,        Aw11 = wxA*wyA;
        const float Alw0 = 1.0f - wzA,            Alw1 = wzA;
        // --- point B coords ---
        const float xB = (gxB + 1.0f) * sc, yB = (gyB + 1.0f) * sc, zB = (gzB + 1.0f) * sc;
        const float xBf = floorf(xB), yBf = floorf(yB), zBf = floorf(zB);
        const float wxB = xB - xBf, wyB = yB - yBf, wzB = zB - zBf;
        const int xB0 = min(max((int)xBf, 0), RES-1); const int xB1 = min(xB0+1, RES-1);
        const int yB0 = min(max((int)yBf, 0), RES-1); const int yB1 = min(yB0+1, RES-1);
        const int zB0 = min(max((int)zBf, 0), RES-1); const int zB1 = min(zB0+1, RES-1);
        const float Bw00 = (1.0f-wxB)*(1.0f-wyB), Bw01 = wxB*(1.0f-wyB);
        const float Bw10 = (1.0f-wxB)*wyB,        Bw11 = wxB*wyB;
        const float Blw0 = 1.0f - wzB,            Blw1 = wzB;

        const __half* P = g_planesH + (size_t)i * RES * RES * NCOMP;
        const __half* L = g_linesH  + (size_t)i * RES * NCOMP;
        const uint4* A00 = (const uint4*)(P + ((size_t)yA0 * RES + xA0) * NCOMP);
        const uint4* A01 = (const uint4*)(P + ((size_t)yA0 * RES + xA1) * NCOMP);
        const uint4* A10 = (const uint4*)(P + ((size_t)yA1 * RES + xA0) * NCOMP);
        const uint4* A11 = (const uint4*)(P + ((size_t)yA1 * RES + xA1) * NCOMP);
        const uint4* AL0 = (const uint4*)(L + (size_t)zA0 * NCOMP);
        const uint4* AL1 = (const uint4*)(L + (size_t)zA1 * NCOMP);
        const uint4* B00 = (const uint4*)(P + ((size_t)yB0 * RES + xB0) * NCOMP);
        const uint4* B01 = (const uint4*)(P + ((size_t)yB0 * RES + xB1) * NCOMP);
        const uint4* B10 = (const uint4*)(P + ((size_t)yB1 * RES + xB0) * NCOMP);
        const uint4* B11 = (const uint4*)(P + ((size_t)yB1 * RES + xB1) * NCOMP);
        const uint4* BL0 = (const uint4*)(L + (size_t)zB0 * NCOMP);
        const uint4* BL1 = (const uint4*)(L + (size_t)zB1 * NCOMP);

        const float* wb = sW + i * NCOMP * NPAD;

        #pragma unroll 1
        for (int c8 = 0; c8 < NCOMP / 8; c8++) {   // 8 channels (one uint4 of halves)
            const uint4 pa00 = A00[c8], pa01 = A01[c8], pa10 = A10[c8], pa11 = A11[c8];
            const uint4 paL0 = AL0[c8], paL1 = AL1[c8];
            const uint4 pb00 = B00[c8], pb01 = B01[c8], pb10 = B10[c8], pb11 = B11[c8];
            const uint4 pbL0 = BL0[c8], pbL1 = BL1[c8];
            const float* wr = wb + (c8 * 8) * NPAD;

            chan_pair2(pa00.x, pa01.x, pa10.x, pa11.x, paL0.x, paL1.x,
                       pb00.x, pb01.x, pb10.x, pb11.x, pbL0.x, pbL1.x,
                       Aw00, Aw01, Aw10, Aw11, Alw0, Alw1,
                       Bw00, Bw01, Bw10, Bw11, Blw0, Blw1,
                       wr + 0 * NPAD, accA, accB);
            chan_pair2(pa00.y, pa01.y, pa10.y, pa11.y, paL0.y, paL1.y,
                       pb00.y, pb01.y, pb10.y, pb11.y, pbL0.y, pbL1.y,
                       Aw00, Aw01, Aw10, Aw11, Alw0, Alw1,
                       Bw00, Bw01, Bw10, Bw11, Blw0, Blw1,
                       wr + 2 * NPAD, accA, accB);
            chan_pair2(pa00.z, pa01.z, pa10.z, pa11.z, paL0.z, paL1.z,
                       pb00.z, pb01.z, pb10.z, pb11.z, pbL0.z, pbL1.z,
                       Aw00, Aw01, Aw10, Aw11, Alw0, Alw1,
                       Bw00, Bw01, Bw10, Bw11, Blw0, Blw1,
                       wr + 4 * NPAD, accA, accB);
            chan_pair2(pa00.w, pa01.w, pa10.w, pa11.w, paL0.w, paL1.w,
                       pb00.w, pb01.w, pb10.w, pb11.w, pbL0.w, pbL1.w,
                       Aw00, Aw01, Aw10, Aw11, Alw0, Alw1,
                       Bw00, Bw01, Bw10, Bw11, Blw0, Blw1,
                       wr + 6 * NPAD, accA, accB);
        }
    }

    // Stage outputs in smem (STS.64 of packed pairs), then coalesced STG.
    {
        float* oA = sOut + tid * OPAD;
        float* oB = sOut + (tid + 128) * OPAD;
        #pragma unroll
        for (int q = 0; q < 14; q++) {
            *reinterpret_cast<unsigned long long*>(oA + 2*q) = accA[q];
            *reinterpret_cast<unsigned long long*>(oB + 2*q) = accB[q];
        }
    }
    __syncthreads();

    for (int e = tid; e < PTS_PER_BLK * NFEAT; e += 128) {
        const int p = e / NFEAT;
        const int j = e - p * NFEAT;
        if (base + p < npts)
            out[(size_t)base * NFEAT + e] = sOut[p * OPAD + j];
    }
}

// ---------------------------------------------------------------------------
extern "C" void kernel_launch(void* const* d_in, const int* in_sizes, int n_in,
                              void* d_out, int out_size) {
    const float* xyz    = (const float*)d_in[0];
    const float* planes = (const float*)d_in[1];
    const float* lines  = (const float*)d_in[2];
    const float* basisW = (const float*)d_in[3];
    float* out = (float*)d_out;
    const int npts = in_sizes[0] / 3;

    dim3 tg((RES + 31) / 32, RES, 3);
    transpose_planes_kernel<<<tg, 256>>>(planes);
    transpose_lines_kernel<<<(3 * RES * NCOMP + 255) / 256, 256>>>(lines);
    const int nblk = (npts + PTS_PER_BLK - 1) / PTS_PER_BLK;
    tvm_main_kernel<<<nblk, 128>>>(xyz, basisW, out, npts);
}

// round 6
// speedup vs baseline: 2.7655x; 1.0767x over previous
#include <cuda_runtime.h>
#include <cuda_fp16.h>
#include <cstdint>

#define RES    300
#define NCOMP  48
#define NFEAT  27
#define KTOT   144
#define NPTS_BLK 512
#define THREADS  768
#define WPAD   28

#define FROWB  352                          // f row stride bytes (16B-mult; phase1 STS conflict-free)
#define F_OFF    0
#define F_BYTES  (NPTS_BLK * FROWB)         // 180224
#define W_OFF    F_BYTES
#define W_BYTES  (KTOT * WPAD * 4)          // 16128
#define XYZ_OFF  (W_OFF + W_BYTES)
#define XYZ_BYTES (NPTS_BLK * 3 * 4)        // 6144
#define SMEM_DYN (XYZ_OFF + XYZ_BYTES)      // 202496 B
#define PSTRIDE  232                        // reduction slot stride (conflict-free)

// Scratch: channel-last transposed fp16 copies.
__device__ __align__(16) __half g_planesH[3u * RES * RES * NCOMP]; // [i][y][x][c]
__device__ __align__(16) __half g_linesH [3u * RES * NCOMP];       // [i][r][c]

// ---------------------------------------------------------------------------
__global__ void transpose_planes_kernel(const float* __restrict__ planes) {
    __shared__ float tile[NCOMP][33];
    const int i  = blockIdx.z;
    const int y  = blockIdx.y;
    const int xt = blockIdx.x * 32;
    const int t  = threadIdx.x;
    const int tx = t & 31;
    const int tc = t >> 5;
    const int x  = xt + tx;
    #pragma unroll
    for (int r = 0; r < 6; r++) {
        const int c = tc + 8 * r;
        if (x < RES)
            tile[c][tx] = planes[(((size_t)i * NCOMP + c) * RES + y) * RES + x];
    }
    __syncthreads();
    const int nx = min(32, RES - xt);
    __half* outb = g_planesH + (((size_t)i * RES + y) * RES + xt) * NCOMP;
    for (int e = t; e < nx * NCOMP; e += 256) {
        const int xl = e / NCOMP;
        const int c  = e - xl * NCOMP;
        outb[e] = __float2half(tile[c][xl]);
    }
}

__global__ void transpose_lines_kernel(const float* __restrict__ lines) {
    const int e = blockIdx.x * 256 + threadIdx.x;
    if (e >= 3 * RES * NCOMP) return;
    const int c  = e % NCOMP;
    const int ir = e / NCOMP;
    const int r  = ir % RES;
    const int i  = ir / RES;
    g_linesH[e] = __float2half(lines[((size_t)i * NCOMP + c) * RES + r]);
}

// ---------------------------------------------------------------------------
__device__ __forceinline__ void fma2(unsigned long long& d,
                                     unsigned long long a,
                                     unsigned long long b) {
    asm("fma.rn.f32x2 %0, %1, %2, %0;" : "+l"(d) : "l"(a), "l"(b));
}
__device__ __forceinline__ unsigned long long pack2(float f) {
    unsigned long long r;
    asm("mov.b64 %0, {%1, %1};" : "=l"(r) : "f"(f));
    return r;
}
__device__ __forceinline__ float2 h2f(uint32_t u) {
    return __half22float2(*reinterpret_cast<const __half2*>(&u));
}
__device__ __forceinline__ uint32_t f2h2(float lo, float hi) {
    uint32_t r;
    asm("cvt.rn.f16x2.f32 %0, %1, %2;" : "=r"(r) : "f"(hi), "f"(lo));
    return r;
}

// ---------------------------------------------------------------------------
// Main: phase1 = 6-lane cooperative gather+interp -> fp16 f in smem;
//       phase2 = (point-pair x k-third) fma2 matvec + reduction.
// ---------------------------------------------------------------------------
__global__ __launch_bounds__(THREADS, 1)
void tvm_main_kernel(const float* __restrict__ xyz,
                     const float* __restrict__ basisW,
                     float* __restrict__ out,
                     int npts) {
    extern __shared__ char sm[];
    float* sW   = reinterpret_cast<float*>(sm + W_OFF);
    float* sXYZ = reinterpret_cast<float*>(sm + XYZ_OFF);

    const int tid  = threadIdx.x;
    const int base = blockIdx.x * NPTS_BLK;

    // Stage W [k][28] (zero pad col) and clamped xyz.
    for (int e = tid; e < KTOT * WPAD; e += THREADS) {
        const int k = e / WPAD;
        const int j = e - k * WPAD;
        sW[e] = (j < NFEAT) ? basisW[j * KTOT + k] : 0.0f;
    }
    for (int e = tid; e < NPTS_BLK * 3; e += THREADS) {
        const int p = e / 3;
        const int c = e - p * 3;
        sXYZ[e] = xyz[(size_t)min(base + p, npts - 1) * 3 + c];
    }
    __syncthreads();

    // ---------------- Phase 1: gather + interp ----------------
    #pragma unroll 1
    for (int it = 0; it < 4; it++) {
        const int s   = tid + it * THREADS;     // 0..3071
        const int p   = s / 6;
        const int c16 = s - p * 6;
        const int co  = c16 * 8;

        const float p0 = sXYZ[p * 3 + 0];
        const float p1 = sXYZ[p * 3 + 1];
        const float p2 = sXYZ[p * 3 + 2];

        #pragma unroll
        for (int i = 0; i < 3; i++) {
            float gx, gy, gz;
            if (i == 0)      { gx = p2; gy = p1; gz = p0; }
            else if (i == 1) { gx = p2; gy = p0; gz = p1; }
            else             { gx = p1; gy = p0; gz = p2; }

            const float sc = 0.5f * (float)(RES - 1);
            const float x = (gx + 1.0f) * sc, y = (gy + 1.0f) * sc, z = (gz + 1.0f) * sc;
            const float xf = floorf(x), yf = floorf(y), zf = floorf(z);
            const float wx = x - xf, wy = y - yf, wz = z - zf;
            const int x0 = min(max((int)xf, 0), RES - 1); const int x1 = min(x0 + 1, RES - 1);
            const int y0 = min(max((int)yf, 0), RES - 1); const int y1 = min(y0 + 1, RES - 1);
            const int z0 = min(max((int)zf, 0), RES - 1); const int z1 = min(z0 + 1, RES - 1);
            const float w00 = (1.0f - wx) * (1.0f - wy);
            const float w01 = wx * (1.0f - wy);
            const float w10 = (1.0f - wx) * wy;
            const float w11 = wx * wy;
            const float lw0 = 1.0f - wz, lw1 = wz;

            const __half* P = g_planesH + (size_t)i * RES * RES * NCOMP;
            const __half* L = g_linesH  + (size_t)i * RES * NCOMP;
            const uint4 t00 = *(const uint4*)(P + ((size_t)y0 * RES + x0) * NCOMP + co);
            const uint4 t01 = *(const uint4*)(P + ((size_t)y0 * RES + x1) * NCOMP + co);
            const uint4 t10 = *(const uint4*)(P + ((size_t)y1 * RES + x0) * NCOMP + co);
            const uint4 t11 = *(const uint4*)(P + ((size_t)y1 * RES + x1) * NCOMP + co);
            const uint4 tL0 = *(const uint4*)(L + (size_t)z0 * NCOMP + co);
            const uint4 tL1 = *(const uint4*)(L + (size_t)z1 * NCOMP + co);

            const uint32_t* a00 = &t00.x; const uint32_t* a01 = &t01.x;
            const uint32_t* a10 = &t10.x; const uint32_t* a11 = &t11.x;
            const uint32_t* aL0 = &tL0.x; const uint32_t* aL1 = &tL1.x;
            uint32_t fw[4];
            #pragma unroll
            for (int w = 0; w < 4; w++) {
                const float2 v00 = h2f(a00[w]), v01 = h2f(a01[w]);
                const float2 v10 = h2f(a10[w]), v11 = h2f(a11[w]);
                const float2 L0  = h2f(aL0[w]), L1  = h2f(aL1[w]);
                const float pf0 = w00*v00.x + w01*v01.x + w10*v10.x + w11*v11.x;
                const float pf1 = w00*v00.y + w01*v01.y + w10*v10.y + w11*v11.y;
                const float lf0 = lw0*L0.x + lw1*L1.x;
                const float lf1 = lw0*L0.y + lw1*L1.y;
                fw[w] = f2h2(pf0 * lf0, pf1 * lf1);
            }
            // f row: halves offset = i*48 + co (contiguous chunks); row stride 352B
            *reinterpret_cast<uint4*>(sm + F_OFF + (size_t)p * FROWB + (i * NCOMP + co) * 2) =
                make_uint4(fw[0], fw[1], fw[2], fw[3]);
        }
    }
    __syncthreads();

    // ---------------- Phase 2: matvec, k split 3 ways ----------------
    const int pp = tid & 255;          // pair id
    const int kt = tid >> 8;           // 0..2  (k third)
    const int ptA = pp;
    const int ptB = pp + 256;

    unsigned long long accA[14], accB[14];
    #pragma unroll
    for (int q = 0; q < 14; q++) { accA[q] = 0ull; accB[q] = 0ull; }

    const char* rowA = sm + F_OFF + (size_t)ptA * FROWB;
    const char* rowB = sm + F_OFF + (size_t)ptB * FROWB;
    const int kbase = kt * NCOMP;      // 48 channels per third

    #pragma unroll 1
    for (int c8 = 0; c8 < 6; c8++) {   // 8 channels per chunk
        const uint4 hA = *reinterpret_cast<const uint4*>(rowA + (kbase + c8 * 8) * 2);
        const uint4 hB = *reinterpret_cast<const uint4*>(rowB + (kbase + c8 * 8) * 2);
        const uint32_t* qa = &hA.x;
        const uint32_t* qb = &hB.x;
        #pragma unroll
        for (int w = 0; w < 4; w++) {  // channel pair
            const int k0 = kbase + c8 * 8 + 2 * w;
            const float2 fa = h2f(qa[w]);
            const float2 fb = h2f(qb[w]);
            const unsigned long long fA0 = pack2(fa.x), fA1 = pack2(fa.y);
            const unsigned long long fB0 = pack2(fb.x), fB1 = pack2(fb.y);
            const ulonglong2* w0 = reinterpret_cast<const ulonglong2*>(sW + k0 * WPAD);
            const ulonglong2* w1 = reinterpret_cast<const ulonglong2*>(sW + (k0 + 1) * WPAD);
            #pragma unroll
            for (int q = 0; q < 7; q++) {
                const ulonglong2 W0 = w0[q];
                fma2(accA[2*q],   W0.x, fA0);
                fma2(accA[2*q+1], W0.y, fA0);
                fma2(accB[2*q],   W0.x, fB0);
                fma2(accB[2*q+1], W0.y, fB0);
                const ulonglong2 W1 = w1[q];
                fma2(accA[2*q],   W1.x, fA1);
                fma2(accA[2*q+1], W1.y, fA1);
                fma2(accB[2*q],   W1.x, fB1);
                fma2(accB[2*q+1], W1.y, fB1);
            }
        }
    }
    __syncthreads();   // all f reads done; fStage reusable

    // partials: kt 1,2 write; kt 0 reduces
    if (kt > 0) {
        unsigned long long* slot = reinterpret_cast<unsigned long long*>(
            sm + ((size_t)((kt - 1) * 256 + pp)) * PSTRIDE);
        #pragma unroll
        for (int q = 0; q < 14; q++) { slot[q] = accA[q]; slot[14 + q] = accB[q]; }
    }
    __syncthreads();
    if (kt == 0) {
        const float* s1 = reinterpret_cast<const float*>(sm + (size_t)pp * PSTRIDE);
        const float* s2 = reinterpret_cast<const float*>(sm + (size_t)(256 + pp) * PSTRIDE);
        float fin[56];
        #pragma unroll
        for (int q = 0; q < 14; q++) {
            float lo, hi;
            asm("mov.b64 {%0, %1}, %2;" : "=f"(lo), "=f"(hi) : "l"(accA[q]));
            fin[2*q]      = lo + s1[2*q]      + s2[2*q];
            fin[2*q + 1]  = hi + s1[2*q + 1]  + s2[2*q + 1];
            asm("mov.b64 {%0, %1}, %2;" : "=f"(lo), "=f"(hi) : "l"(accB[q]));
            fin[28 + 2*q]     = lo + s1[28 + 2*q]     + s2[28 + 2*q];
            fin[28 + 2*q + 1] = hi + s1[28 + 2*q + 1] + s2[28 + 2*q + 1];
        }
        float* dst = reinterpret_cast<float*>(sm + (size_t)pp * PSTRIDE);
        #pragma unroll
        for (int q = 0; q < 56; q++) dst[q] = fin[q];
    }
    __syncthreads();

    // coalesced store
    for (int e = tid; e < NPTS_BLK * NFEAT; e += THREADS) {
        const int pt = e / NFEAT;
        const int j  = e - pt * NFEAT;
        if (base + pt < npts) {
            const int pq   = pt & 255;
            const int half = pt >> 8;
            out[(size_t)(base + pt) * NFEAT + j] =
                *reinterpret_cast<const float*>(sm + (size_t)pq * PSTRIDE + (half * 28 + j) * 4);
        }
    }
}

// ---------------------------------------------------------------------------
extern "C" void kernel_launch(void* const* d_in, const int* in_sizes, int n_in,
                              void* d_out, int out_size) {
    const float* xyz    = (const float*)d_in[0];
    const float* planes = (const float*)d_in[1];
    const float* lines  = (const float*)d_in[2];
    const float* basisW = (const float*)d_in[3];
    float* out = (float*)d_out;
    const int npts = in_sizes[0] / 3;

    cudaFuncSetAttribute(tvm_main_kernel,
                         cudaFuncAttributeMaxDynamicSharedMemorySize, SMEM_DYN);

    dim3 tg((RES + 31) / 32, RES, 3);
    transpose_planes_kernel<<<tg, 256>>>(planes);
    transpose_lines_kernel<<<(3 * RES * NCOMP + 255) / 256, 256>>>(lines);
    const int nblk = (npts + NPTS_BLK - 1) / NPTS_BLK;
    tvm_main_kernel<<<nblk, THREADS, SMEM_DYN>>>(xyz, basisW, out, npts);
}